// round 9
// baseline (speedup 1.0000x reference)
#include <cuda_runtime.h>
#include <cuda_fp16.h>
#include <cstdint>

#define C_IN    128
#define C_OUT   64
#define KOFF    27
#define M_PAIRS 100000
#define N_ROWS  100000
#define N_OUTP  200000
#define BN_EPS  1e-5f

// ---------------- device scratch (allocation-free) --------------------------
__device__ __half g_Xh[(size_t)N_ROWS * C_IN];      // 25.6 MB, L2-resident
__device__ __half g_Wh[(size_t)KOFF * C_OUT * C_IN];// [k][co][ci], 0.44 MB
__device__ float g_sum[C_OUT], g_sumsq[C_OUT];

// ---------------- PTX helpers ----------------------------------------------
__device__ __forceinline__ uint32_t smem_u32(const void* p) {
    uint32_t a;
    asm("{ .reg .u64 t; cvta.to.shared.u64 t, %1; cvt.u32.u64 %0, t; }" : "=r"(a) : "l"(p));
    return a;
}
#define BULK_CP(dst, src, bytes, mbar) \
    asm volatile("cp.async.bulk.shared::cluster.global.mbarrier::complete_tx::bytes " \
        "[%0], [%1], %2, [%3];" :: "r"(dst), "l"(src), "r"(bytes), "r"(mbar) : "memory")

#define MBAR_INIT(a, c) \
    asm volatile("mbarrier.init.shared.b64 [%0], %1;" :: "r"(a), "r"(c) : "memory")
#define MBAR_EXPECT_TX(a, tx) \
    asm volatile("mbarrier.arrive.expect_tx.shared.b64 _, [%0], %1;" :: "r"(a), "r"(tx) : "memory")
#define MBAR_ARRIVE(a) \
    asm volatile("mbarrier.arrive.shared.b64 _, [%0];" :: "r"(a) : "memory")
#define MBAR_WAIT(a, ph) do {                                                   \
    asm volatile("{ .reg .pred P; WL%=:"                                        \
        " mbarrier.try_wait.parity.acquire.cta.shared::cta.b64 P, [%0], %1, 0x989680;" \
        " @P bra.uni WD%=; bra.uni WL%=; WD%=: }"                               \
        :: "r"(a), "r"(ph) : "memory");                                         \
} while (0)

#define LDMATRIX_X4(r, addr) \
    asm volatile("ldmatrix.sync.aligned.m8n8.x4.shared.b16 {%0,%1,%2,%3}, [%4];" \
        : "=r"((r)[0]), "=r"((r)[1]), "=r"((r)[2]), "=r"((r)[3]) : "r"(addr))

#define MMA16816(d, a, b0, b1) \
    asm volatile("mma.sync.aligned.m16n8k16.row.col.f32.f16.f16.f32 " \
        "{%0,%1,%2,%3}, {%4,%5,%6,%7}, {%8,%9}, {%0,%1,%2,%3};" \
        : "+f"((d)[0]), "+f"((d)[1]), "+f"((d)[2]), "+f"((d)[3]) \
        : "r"((a)[0]), "r"((a)[1]), "r"((a)[2]), "r"((a)[3]), "r"(b0), "r"(b1))

// ---------------- prep: x->fp16 + zero out | w->fp16(T) + zero stats --------
#define XBLKS 12500

__global__ void __launch_bounds__(256)
prep_kernel(const float* __restrict__ x,
            const float* __restrict__ w,
            float* __restrict__ out,
            int out_n4)
{
    const int gid = blockIdx.x;
    if (gid < XBLKS) {
        const int idx = gid * 256 + threadIdx.x;
        float4 v = ((const float4*)x)[idx];
        __half2* dst = (__half2*)(g_Xh + (size_t)idx * 4);
        dst[0] = __floats2half2_rn(v.x, v.y);
        dst[1] = __floats2half2_rn(v.z, v.w);
        if (idx < out_n4)
            ((float4*)out)[idx] = make_float4(0.f, 0.f, 0.f, 0.f);
    } else {
        const int j = (gid - XBLKS) * 256 + threadIdx.x;
        if (j < C_OUT) { g_sum[j] = 0.f; g_sumsq[j] = 0.f; }
        if (j < KOFF * C_IN * C_OUT) {
            const int k  = j / (C_IN * C_OUT);
            const int r  = j % (C_IN * C_OUT);
            const int ci = r / C_OUT, co = r % C_OUT;
            g_Wh[(size_t)k * (C_OUT * C_IN) + co * C_IN + ci] = __float2half_rn(w[j]);
        }
    }
}

// ---------------- persistent fused: ring-buffered gather + HMMA + scatter ---
// grid = 148 CTAs x 320 threads (10 warps). Tile = 320 pairs x 64 cols, K=128.
// 2 smem stages (A 87040 + B 17408 each) -> 1 CTA/SM, depth-2 pipeline:
// loads for tile i+2 issued right after the LDSM phase of tile i frees stage.
// Per-pair LDSM/MMA/RED op counts identical to the proven R5 kernel.
#define PAIRS_TILE 320
#define NTILE_K    ((M_PAIRS + PAIRS_TILE - 1) / PAIRS_TILE)   // 313
#define NTILES     (KOFF * NTILE_K)                            // 8451
#define GRID_P     148
#define ROWB       272
#define STAGE_A    (PAIRS_TILE * ROWB)                         // 87040
#define STAGE_B    (64 * ROWB)                                 // 17408
#define STAGE_SZ   (STAGE_A + STAGE_B)                         // 104448
#define SM_STAGE   64
#define SMEM_P     (SM_STAGE + 2 * STAGE_SZ)                   // 208960

__global__ void __launch_bounds__(PAIRS_TILE, 1)
fused_kernel(const int* __restrict__ in_map,
             const int* __restrict__ out_map,
             float* __restrict__ out)
{
    extern __shared__ char smem[];
    const uint32_t sbase = smem_u32(smem);
    const uint32_t full_b[2]  = { sbase + 0,  sbase + 8  };
    const uint32_t empty_b[2] = { sbase + 16, sbase + 24 };

    const int t    = threadIdx.x;
    const int lane = t & 31;
    const int w    = t >> 5;

    if (t == 0) {
        MBAR_INIT(full_b[0],  PAIRS_TILE); MBAR_INIT(full_b[1],  PAIRS_TILE);
        MBAR_INIT(empty_b[0], PAIRS_TILE); MBAR_INIT(empty_b[1], PAIRS_TILE);
    }
    __syncthreads();

    int pf[2] = { 0, 0 }, pe[2] = { 0, 0 };
    int om_arr[2] = { -1, -1 };

    // issue loads for job index i (global tile g = bid + i*GRID_P); returns om
    auto do_load = [&](int i) -> int {
        const int g = blockIdx.x + i * GRID_P;
        if (g >= NTILES) return -1;
        const int s = i & 1;
        if (i >= 2) { MBAR_WAIT(empty_b[s], pe[s]); pe[s] ^= 1; }
        const int k    = g % KOFF;
        const int tile = g / KOFF;
        const int p    = tile * PAIRS_TILE + t;
        const int ok   = (p < M_PAIRS);
        const int pc   = ok ? p : (M_PAIRS - 1);
        const int im   = in_map[k * M_PAIRS + pc];
        const int om   = ok ? out_map[k * M_PAIRS + pc] : -1;
        const uint32_t stg = sbase + SM_STAGE + s * STAGE_SZ;
        // per-thread expect_tx for its own bytes, then issue
        MBAR_EXPECT_TX(full_b[s], (t < 64) ? 512u : 256u);
        BULK_CP(stg + t * ROWB, g_Xh + (size_t)im * C_IN, 256, full_b[s]);
        if (t < 64)
            BULK_CP(stg + STAGE_A + t * ROWB,
                    g_Wh + ((size_t)k * C_OUT + t) * C_IN, 256, full_b[s]);
        return om;
    };

    om_arr[0] = do_load(0);
    om_arr[1] = do_load(1);

    for (int i = 0;; ++i) {
        const int g = blockIdx.x + i * GRID_P;
        if (g >= NTILES) break;
        const int s  = i & 1;
        const int om = om_arr[s];

        MBAR_WAIT(full_b[s], pf[s]); pf[s] ^= 1;
        const uint32_t abase = sbase + SM_STAGE + s * STAGE_SZ;
        const uint32_t bbase = abase + STAGE_A;

        // ---- MMA: warp w owns rows [32w, 32w+32), cols 0..63 ----
        float d[2][8][4];
        #pragma unroll
        for (int mt = 0; mt < 2; ++mt)
            #pragma unroll
            for (int nt = 0; nt < 8; ++nt)
                #pragma unroll
                for (int j = 0; j < 4; ++j) d[mt][nt][j] = 0.f;

        #pragma unroll
        for (int kc = 0; kc < 8; ++kc) {
            uint32_t a_frag[2][4];
            #pragma unroll
            for (int mt = 0; mt < 2; ++mt) {
                int row = w * 32 + mt * 16 + (lane & 15);
                int ch  = kc * 2 + (lane >> 4);
                LDMATRIX_X4(a_frag[mt], abase + row * ROWB + ch * 16);
            }
            uint32_t b_frag[4][4];
            #pragma unroll
            for (int nt2 = 0; nt2 < 4; ++nt2) {
                int n  = nt2 * 16 + ((lane >> 4) << 3) + (lane & 7);
                int ch = kc * 2 + ((lane >> 3) & 1);
                LDMATRIX_X4(b_frag[nt2], bbase + n * ROWB + ch * 16);
            }
            #pragma unroll
            for (int mt = 0; mt < 2; ++mt)
                #pragma unroll
                for (int nt = 0; nt < 8; ++nt)
                    MMA16816(d[mt][nt], a_frag[mt],
                             b_frag[nt >> 1][(nt & 1) * 2],
                             b_frag[nt >> 1][(nt & 1) * 2 + 1]);
        }

        // stage s fully consumed (all LDSM returned) -> free it, refill it
        MBAR_ARRIVE(empty_b[s]);
        om_arr[s] = do_load(i + 2);

        // ---- scatter-add from fragments (overlaps the TMA just issued) ----
        #pragma unroll
        for (int mt = 0; mt < 2; ++mt) {
            const int src = mt * 16 + (lane >> 2);
            const int om0 = __shfl_sync(0xffffffffu, om, src);
            const int om1 = __shfl_sync(0xffffffffu, om, src + 8);
            float* dst0 = out + (size_t)om0 * C_OUT + (lane & 3) * 2;
            float* dst1 = out + (size_t)om1 * C_OUT + (lane & 3) * 2;
            #pragma unroll
            for (int nt = 0; nt < 8; ++nt) {
                if (om0 >= 0)
                    asm volatile("red.global.add.v2.f32 [%0], {%1,%2};"
                                 :: "l"(dst0 + nt * 8), "f"(d[mt][nt][0]), "f"(d[mt][nt][1])
                                 : "memory");
                if (om1 >= 0)
                    asm volatile("red.global.add.v2.f32 [%0], {%1,%2};"
                                 :: "l"(dst1 + nt * 8), "f"(d[mt][nt][2]), "f"(d[mt][nt][3])
                                 : "memory");
            }
        }
    }
}

// ---------------- BN stats (R5-proven scalar form) --------------------------
__global__ void __launch_bounds__(256)
stats_kernel(const float* __restrict__ out)
{
    __shared__ float ss[256], sq[256];
    const int t = threadIdx.x, ch = t & 63, rep = t >> 6;
    float s = 0.f, q = 0.f;
    #pragma unroll 4
    for (int row = blockIdx.x * 4 + rep; row < N_OUTP; row += gridDim.x * 4) {
        const float v = out[(size_t)row * C_OUT + ch];
        s += v; q = fmaf(v, v, q);
    }
    ss[t] = s; sq[t] = q;
    __syncthreads();
    if (t < 64) {
        atomicAdd(&g_sum[t],   ss[t] + ss[t + 64] + ss[t + 128] + ss[t + 192]);
        atomicAdd(&g_sumsq[t], sq[t] + sq[t + 64] + sq[t + 128] + sq[t + 192]);
    }
}

// ---------------- normalize + ReLU (finalize folded in) ---------------------
__global__ void __launch_bounds__(256)
normalize_kernel(float* __restrict__ out,
                 const float* __restrict__ gamma,
                 const float* __restrict__ beta)
{
    __shared__ float sc[C_OUT], bs[C_OUT];
    if (threadIdx.x < C_OUT) {
        const int c = threadIdx.x;
        const float inv_n = 1.0f / (float)N_OUTP;
        const float mean = g_sum[c] * inv_n;
        const float var  = g_sumsq[c] * inv_n - mean * mean;
        const float s    = gamma[c] * rsqrtf(var + BN_EPS);
        sc[c] = s;
        bs[c] = beta[c] - mean * s;
    }
    __syncthreads();
    const int total4 = N_OUTP * C_OUT / 4;
    for (int i = blockIdx.x * blockDim.x + threadIdx.x; i < total4;
         i += gridDim.x * blockDim.x) {
        float4 v = ((float4*)out)[i];
        const int c0 = (i * 4) & 63;
        v.x = fmaxf(fmaf(v.x, sc[c0 + 0], bs[c0 + 0]), 0.f);
        v.y = fmaxf(fmaf(v.y, sc[c0 + 1], bs[c0 + 1]), 0.f);
        v.z = fmaxf(fmaf(v.z, sc[c0 + 2], bs[c0 + 2]), 0.f);
        v.w = fmaxf(fmaf(v.w, sc[c0 + 3], bs[c0 + 3]), 0.f);
        ((float4*)out)[i] = v;
    }
}

// ---------------- launch ----------------------------------------------------
extern "C" void kernel_launch(void* const* d_in, const int* in_sizes, int n_in,
                              void* d_out, int out_size)
{
    const float* x       = (const float*)d_in[0];
    const float* weight  = (const float*)d_in[1];
    const float* gamma   = (const float*)d_in[2];
    const float* beta    = (const float*)d_in[3];
    const int*   in_map  = (const int*)d_in[4];
    const int*   out_map = (const int*)d_in[5];
    float*       out     = (float*)d_out;

    cudaFuncSetAttribute(fused_kernel, cudaFuncAttributeMaxDynamicSharedMemorySize,
                         SMEM_P);

    const int wblks = (KOFF * C_IN * C_OUT + 255) / 256;       // 864
    prep_kernel<<<XBLKS + wblks, 256>>>(x, weight, out, out_size / 4);

    fused_kernel<<<GRID_P, PAIRS_TILE, SMEM_P>>>(in_map, out_map, out);

    stats_kernel<<<1184, 256>>>(out);
    normalize_kernel<<<2048, 256>>>(out, gamma, beta);
}

// round 10
// speedup vs baseline: 1.4870x; 1.4870x over previous
#include <cuda_runtime.h>
#include <cuda_fp16.h>
#include <cstdint>

#define C_IN    128
#define C_OUT   64
#define KOFF    27
#define M_PAIRS 100000
#define N_ROWS  100000
#define N_OUTP  200000
#define BN_EPS  1e-5f

// ---------------- device scratch (allocation-free) --------------------------
__device__ __half g_Xh[(size_t)N_ROWS * C_IN];      // 25.6 MB, L2-resident
__device__ __half g_Wh[(size_t)KOFF * C_OUT * C_IN];// [k][co][ci], 0.44 MB
__device__ float g_sum[C_OUT], g_sumsq[C_OUT];

// ---------------- PTX helpers ----------------------------------------------
__device__ __forceinline__ uint32_t smem_u32(const void* p) {
    uint32_t a;
    asm("{ .reg .u64 t; cvta.to.shared.u64 t, %1; cvt.u32.u64 %0, t; }" : "=r"(a) : "l"(p));
    return a;
}
#define BULK_CP(dst, src, bytes, mbar) \
    asm volatile("cp.async.bulk.shared::cluster.global.mbarrier::complete_tx::bytes " \
        "[%0], [%1], %2, [%3];" :: "r"(dst), "l"(src), "r"(bytes), "r"(mbar) : "memory")

#define MBAR_INIT(a, c) \
    asm volatile("mbarrier.init.shared.b64 [%0], %1;" :: "r"(a), "r"(c) : "memory")
#define MBAR_EXPECT_TX(a, tx) \
    asm volatile("mbarrier.arrive.expect_tx.shared.b64 _, [%0], %1;" :: "r"(a), "r"(tx) : "memory")
#define MBAR_WAIT(a, ph) do {                                                   \
    asm volatile("{ .reg .pred P; WL%=:"                                        \
        " mbarrier.try_wait.parity.acquire.cta.shared::cta.b64 P, [%0], %1, 0x989680;" \
        " @P bra.uni WD%=; bra.uni WL%=; WD%=: }"                               \
        :: "r"(a), "r"(ph) : "memory");                                         \
} while (0)

#define LDMATRIX_X4(r, addr) \
    asm volatile("ldmatrix.sync.aligned.m8n8.x4.shared.b16 {%0,%1,%2,%3}, [%4];" \
        : "=r"((r)[0]), "=r"((r)[1]), "=r"((r)[2]), "=r"((r)[3]) : "r"(addr))

#define MMA16816(d, a, b0, b1) \
    asm volatile("mma.sync.aligned.m16n8k16.row.col.f32.f16.f16.f32 " \
        "{%0,%1,%2,%3}, {%4,%5,%6,%7}, {%8,%9}, {%0,%1,%2,%3};" \
        : "+f"((d)[0]), "+f"((d)[1]), "+f"((d)[2]), "+f"((d)[3]) \
        : "r"((a)[0]), "r"((a)[1]), "r"((a)[2]), "r"((a)[3]), "r"(b0), "r"(b1))

// ---------------- prep: x->fp16 + zero out | w->fp16(T) + zero stats --------
// blocks [0, 12500): convert one x float4 AND zero the matching out float4.
// blocks [12500, 13364): convert w (27*128*64 elems) + zero stats.
#define XBLKS 12500

__global__ void __launch_bounds__(256)
prep_kernel(const float* __restrict__ x,
            const float* __restrict__ w,
            float* __restrict__ out,
            int out_n4)
{
    const int gid = blockIdx.x;
    if (gid < XBLKS) {
        const int idx = gid * 256 + threadIdx.x;
        float4 v = ((const float4*)x)[idx];
        __half2* dst = (__half2*)(g_Xh + (size_t)idx * 4);
        dst[0] = __floats2half2_rn(v.x, v.y);
        dst[1] = __floats2half2_rn(v.z, v.w);
        if (idx < out_n4)
            ((float4*)out)[idx] = make_float4(0.f, 0.f, 0.f, 0.f);
    } else {
        const int j = (gid - XBLKS) * 256 + threadIdx.x;
        if (j < C_OUT) { g_sum[j] = 0.f; g_sumsq[j] = 0.f; }
        if (j < KOFF * C_IN * C_OUT) {
            const int k  = j / (C_IN * C_OUT);
            const int r  = j % (C_IN * C_OUT);
            const int ci = r / C_OUT, co = r % C_OUT;
            g_Wh[(size_t)k * (C_OUT * C_IN) + co * C_IN + ci] = __float2half_rn(w[j]);
        }
    }
}

// ---------------- fused gather(bulk) + HMMA + direct-frag scatter -----------
// R8-proven: grid = (521 pair-blocks, 27 offsets); block = 192 threads.
// Tile: 192 pairs x 64 out-channels, K = 128. Warp w owns rows [32w, 32w+32).
// Split barriers; 272B smem rows -> conflict-free ldmatrix; 3 CTAs/SM give
// the cross-CTA gather/MMA/RED overlap (R9 showed 1-CTA pipelining loses it).
#define PAIRS_BLK 192
#define ROWB      272
#define SM_MBAR0  0
#define SM_MBAR1  8
#define SM_A      32
#define SM_B      (SM_A + PAIRS_BLK * ROWB)     // 52256
#define SMEM_FUSED (SM_B + 64 * ROWB)           // 69664

__global__ void __launch_bounds__(PAIRS_BLK)
fused_kernel(const int* __restrict__ in_map,
             const int* __restrict__ out_map,
             float* __restrict__ out)
{
    extern __shared__ char smem[];
    const uint32_t sbase = smem_u32(smem);
    const uint32_t abase = sbase + SM_A;
    const uint32_t bbase = sbase + SM_B;

    const int t    = threadIdx.x;
    const int lane = t & 31;
    const int w    = t >> 5;
    const int k    = blockIdx.y;

    // ---- pair indices (thread t owns pair-row t) ----
    const int p     = blockIdx.x * PAIRS_BLK + t;
    const int valid = (p < M_PAIRS);
    const int pc    = valid ? p : (M_PAIRS - 1);
    const int im    = in_map [k * M_PAIRS + pc];
    const int om    = valid ? out_map[k * M_PAIRS + pc] : -1;

    if (t == 0) { MBAR_INIT(sbase + SM_MBAR0, 1); MBAR_INIT(sbase + SM_MBAR1, 1); }
    __syncthreads();
    if (t == 0) MBAR_EXPECT_TX(sbase + SM_MBAR0, 96 * 256 + 64 * 256);
    if (t == 1) MBAR_EXPECT_TX(sbase + SM_MBAR1, 96 * 256);

    // ---- gather A: one 256B bulk per row; B rows by threads 0..63 ----
    const uint32_t mybar = sbase + (t < 96 ? SM_MBAR0 : SM_MBAR1);
    BULK_CP(abase + t * ROWB, g_Xh + (size_t)im * C_IN, 256, mybar);
    if (t < 64)
        BULK_CP(bbase + t * ROWB, g_Wh + ((size_t)k * C_OUT + t) * C_IN, 256,
                sbase + SM_MBAR0);

    MBAR_WAIT(sbase + SM_MBAR0, 0);
    if (w >= 3) MBAR_WAIT(sbase + SM_MBAR1, 0);

    // ---- MMA mainloop: warp w owns rows [32w, 32w+32), cols 0..63 ----
    float d[2][8][4];
    #pragma unroll
    for (int mt = 0; mt < 2; ++mt)
        #pragma unroll
        for (int nt = 0; nt < 8; ++nt)
            #pragma unroll
            for (int j = 0; j < 4; ++j) d[mt][nt][j] = 0.f;

    #pragma unroll
    for (int kc = 0; kc < 8; ++kc) {
        uint32_t a_frag[2][4];
        #pragma unroll
        for (int mt = 0; mt < 2; ++mt) {
            int row = w * 32 + mt * 16 + (lane & 15);
            int ch  = kc * 2 + (lane >> 4);
            LDMATRIX_X4(a_frag[mt], abase + row * ROWB + ch * 16);
        }
        uint32_t b_frag[4][4];
        #pragma unroll
        for (int nt2 = 0; nt2 < 4; ++nt2) {
            int n  = nt2 * 16 + ((lane >> 4) << 3) + (lane & 7);
            int ch = kc * 2 + ((lane >> 3) & 1);
            LDMATRIX_X4(b_frag[nt2], bbase + n * ROWB + ch * 16);
        }
        #pragma unroll
        for (int mt = 0; mt < 2; ++mt)
            #pragma unroll
            for (int nt = 0; nt < 8; ++nt)
                MMA16816(d[mt][nt], a_frag[mt],
                         b_frag[nt >> 1][(nt & 1) * 2],
                         b_frag[nt >> 1][(nt & 1) * 2 + 1]);
    }

    // ---- scatter-add straight from fragments; out rows fetched via shfl ----
    #pragma unroll
    for (int mt = 0; mt < 2; ++mt) {
        const int src  = mt * 16 + (lane >> 2);
        const int om0  = __shfl_sync(0xffffffffu, om, src);
        const int om1  = __shfl_sync(0xffffffffu, om, src + 8);
        float* dst0 = out + (size_t)om0 * C_OUT + (lane & 3) * 2;
        float* dst1 = out + (size_t)om1 * C_OUT + (lane & 3) * 2;
        #pragma unroll
        for (int nt = 0; nt < 8; ++nt) {
            if (om0 >= 0)
                asm volatile("red.global.add.v2.f32 [%0], {%1,%2};"
                             :: "l"(dst0 + nt * 8), "f"(d[mt][nt][0]), "f"(d[mt][nt][1])
                             : "memory");
            if (om1 >= 0)
                asm volatile("red.global.add.v2.f32 [%0], {%1,%2};"
                             :: "l"(dst1 + nt * 8), "f"(d[mt][nt][2]), "f"(d[mt][nt][3])
                             : "memory");
        }
    }
}

// ---------------- BN stats: float4 loads, one sync --------------------------
// Thread t owns channels (t&15)*4..+3, row-replica t>>4 (16 reps/block).
// Partials to smem [rep][ch] once, single __syncthreads, 64-thread reduce.
__global__ void __launch_bounds__(256)
stats_kernel(const float* __restrict__ out)
{
    __shared__ float ss[16 * C_OUT], sq[16 * C_OUT];   // 2 x 4 KB
    const int t   = threadIdx.x;
    const int c4  = (t & 15) * 4;
    const int rep = t >> 4;
    float4 s = make_float4(0.f, 0.f, 0.f, 0.f);
    float4 q = make_float4(0.f, 0.f, 0.f, 0.f);
    for (int row = blockIdx.x * 16 + rep; row < N_OUTP; row += gridDim.x * 16) {
        const float4 v = *(const float4*)(out + (size_t)row * C_OUT + c4);
        s.x += v.x; q.x = fmaf(v.x, v.x, q.x);
        s.y += v.y; q.y = fmaf(v.y, v.y, q.y);
        s.z += v.z; q.z = fmaf(v.z, v.z, q.z);
        s.w += v.w; q.w = fmaf(v.w, v.w, q.w);
    }
    *(float4*)&ss[rep * C_OUT + c4] = s;
    *(float4*)&sq[rep * C_OUT + c4] = q;
    __syncthreads();
    if (t < C_OUT) {
        float as = 0.f, aq = 0.f;
        #pragma unroll
        for (int r = 0; r < 16; ++r) {
            as += ss[r * C_OUT + t];
            aq += sq[r * C_OUT + t];
        }
        atomicAdd(&g_sum[t],   as);
        atomicAdd(&g_sumsq[t], aq);
    }
}

// ---------------- normalize + ReLU (finalize folded in) ---------------------
__global__ void __launch_bounds__(256)
normalize_kernel(float* __restrict__ out,
                 const float* __restrict__ gamma,
                 const float* __restrict__ beta)
{
    __shared__ float sc[C_OUT], bs[C_OUT];
    if (threadIdx.x < C_OUT) {
        const int c = threadIdx.x;
        const float inv_n = 1.0f / (float)N_OUTP;
        const float mean = g_sum[c] * inv_n;
        const float var  = g_sumsq[c] * inv_n - mean * mean;
        const float s    = gamma[c] * rsqrtf(var + BN_EPS);
        sc[c] = s;
        bs[c] = beta[c] - mean * s;
    }
    __syncthreads();
    const int total4 = N_OUTP * C_OUT / 4;
    for (int i = blockIdx.x * blockDim.x + threadIdx.x; i < total4;
         i += gridDim.x * blockDim.x) {
        float4 v = ((float4*)out)[i];
        const int c0 = (i * 4) & 63;
        v.x = fmaxf(fmaf(v.x, sc[c0 + 0], bs[c0 + 0]), 0.f);
        v.y = fmaxf(fmaf(v.y, sc[c0 + 1], bs[c0 + 1]), 0.f);
        v.z = fmaxf(fmaf(v.z, sc[c0 + 2], bs[c0 + 2]), 0.f);
        v.w = fmaxf(fmaf(v.w, sc[c0 + 3], bs[c0 + 3]), 0.f);
        ((float4*)out)[i] = v;
    }
}

// ---------------- launch ----------------------------------------------------
extern "C" void kernel_launch(void* const* d_in, const int* in_sizes, int n_in,
                              void* d_out, int out_size)
{
    const float* x       = (const float*)d_in[0];
    const float* weight  = (const float*)d_in[1];
    const float* gamma   = (const float*)d_in[2];
    const float* beta    = (const float*)d_in[3];
    const int*   in_map  = (const int*)d_in[4];
    const int*   out_map = (const int*)d_in[5];
    float*       out     = (float*)d_out;

    cudaFuncSetAttribute(fused_kernel, cudaFuncAttributeMaxDynamicSharedMemorySize,
                         SMEM_FUSED);

    const int wblks = (KOFF * C_IN * C_OUT + 255) / 256;       // 864
    prep_kernel<<<XBLKS + wblks, 256>>>(x, weight, out, out_size / 4);

    {
        dim3 grid((M_PAIRS + PAIRS_BLK - 1) / PAIRS_BLK, KOFF);
        fused_kernel<<<grid, PAIRS_BLK, SMEM_FUSED>>>(in_map, out_map, out);
    }

    stats_kernel<<<1184, 256>>>(out);
    normalize_kernel<<<2048, 256>>>(out, gamma, beta);
}

// round 11
// speedup vs baseline: 1.5209x; 1.0227x over previous
#include <cuda_runtime.h>
#include <cuda_fp16.h>
#include <cstdint>

#define C_IN    128
#define C_OUT   64
#define KOFF    27
#define M_PAIRS 100000
#define N_ROWS  100000
#define N_OUTP  200000
#define BN_EPS  1e-5f

// ---------------- device scratch (allocation-free) --------------------------
__device__ __half g_Xh[(size_t)N_ROWS * C_IN];            // 25.6 MB, L2-resident
// B pre-strided in smem image layout: [k][co][136 halves] (272 B rows)
__device__ __align__(256) __half g_Wsw[(size_t)KOFF * C_OUT * 136];
__device__ float g_sum[C_OUT], g_sumsq[C_OUT];

// ---------------- PTX helpers ----------------------------------------------
__device__ __forceinline__ uint32_t smem_u32(const void* p) {
    uint32_t a;
    asm("{ .reg .u64 t; cvta.to.shared.u64 t, %1; cvt.u32.u64 %0, t; }" : "=r"(a) : "l"(p));
    return a;
}
#define BULK_CP(dst, src, bytes, mbar) \
    asm volatile("cp.async.bulk.shared::cluster.global.mbarrier::complete_tx::bytes " \
        "[%0], [%1], %2, [%3];" :: "r"(dst), "l"(src), "r"(bytes), "r"(mbar) : "memory")

#define MBAR_INIT(a, c) \
    asm volatile("mbarrier.init.shared.b64 [%0], %1;" :: "r"(a), "r"(c) : "memory")
#define MBAR_EXPECT_TX(a, tx) \
    asm volatile("mbarrier.arrive.expect_tx.shared.b64 _, [%0], %1;" :: "r"(a), "r"(tx) : "memory")
#define MBAR_WAIT(a, ph) do {                                                   \
    asm volatile("{ .reg .pred P; WL%=:"                                        \
        " mbarrier.try_wait.parity.acquire.cta.shared::cta.b64 P, [%0], %1, 0x989680;" \
        " @P bra.uni WD%=; bra.uni WL%=; WD%=: }"                               \
        :: "r"(a), "r"(ph) : "memory");                                         \
} while (0)

#define LDMATRIX_X4(r, addr) \
    asm volatile("ldmatrix.sync.aligned.m8n8.x4.shared.b16 {%0,%1,%2,%3}, [%4];" \
        : "=r"((r)[0]), "=r"((r)[1]), "=r"((r)[2]), "=r"((r)[3]) : "r"(addr))

#define MMA16816(d, a, b0, b1) \
    asm volatile("mma.sync.aligned.m16n8k16.row.col.f32.f16.f16.f32 " \
        "{%0,%1,%2,%3}, {%4,%5,%6,%7}, {%8,%9}, {%0,%1,%2,%3};" \
        : "+f"((d)[0]), "+f"((d)[1]), "+f"((d)[2]), "+f"((d)[3]) \
        : "r"((a)[0]), "r"((a)[1]), "r"((a)[2]), "r"((a)[3]), "r"(b0), "r"(b1))

// ---------------- prep: x->fp16 + zero out | w->strided fp16 + zero stats ---
// blocks [0, 12500): convert one x float4 AND zero the matching out float4.
// blocks [12500, 13364): w -> g_Wsw smem-image layout + zero stats.
#define XBLKS 12500

__global__ void __launch_bounds__(256)
prep_kernel(const float* __restrict__ x,
            const float* __restrict__ w,
            float* __restrict__ out,
            int out_n4)
{
    const int gid = blockIdx.x;
    if (gid < XBLKS) {
        const int idx = gid * 256 + threadIdx.x;
        float4 v = ((const float4*)x)[idx];
        __half2* dst = (__half2*)(g_Xh + (size_t)idx * 4);
        dst[0] = __floats2half2_rn(v.x, v.y);
        dst[1] = __floats2half2_rn(v.z, v.w);
        if (idx < out_n4)
            ((float4*)out)[idx] = make_float4(0.f, 0.f, 0.f, 0.f);
    } else {
        const int j = (gid - XBLKS) * 256 + threadIdx.x;
        if (j < C_OUT) { g_sum[j] = 0.f; g_sumsq[j] = 0.f; }
        if (j < KOFF * C_IN * C_OUT) {
            const int k  = j / (C_IN * C_OUT);
            const int r  = j % (C_IN * C_OUT);
            const int ci = r / C_OUT, co = r % C_OUT;
            // smem image: row co is 136 halves (272 B), first 128 carry data
            g_Wsw[(size_t)k * (C_OUT * 136) + co * 136 + ci] = __float2half_rn(w[j]);
        }
    }
}

// ---------------- fused gather(bulk) + HMMA + direct-frag scatter -----------
// R8/R10-proven shape: grid = (521, 27); block = 192 threads (6 warps).
// Tile: 192 pairs x 64 out-channels, K = 128. Warp w owns rows [32w, 32w+32).
// B now lands via ONE 17408B bulk-cp (pre-strided in g_Wsw) instead of 64 ops.
#define PAIRS_BLK 192
#define ROWB      272
#define SM_MBAR0  0
#define SM_MBAR1  8
#define SM_A      32
#define SM_B      (SM_A + PAIRS_BLK * ROWB)     // 52256
#define B_BYTES   (64 * ROWB)                   // 17408
#define SMEM_FUSED (SM_B + B_BYTES)             // 69664

__global__ void __launch_bounds__(PAIRS_BLK)
fused_kernel(const int* __restrict__ in_map,
             const int* __restrict__ out_map,
             float* __restrict__ out)
{
    extern __shared__ char smem[];
    const uint32_t sbase = smem_u32(smem);
    const uint32_t abase = sbase + SM_A;
    const uint32_t bbase = sbase + SM_B;

    const int t    = threadIdx.x;
    const int lane = t & 31;
    const int w    = t >> 5;
    const int k    = blockIdx.y;

    // ---- pair indices (thread t owns pair-row t) ----
    const int p     = blockIdx.x * PAIRS_BLK + t;
    const int valid = (p < M_PAIRS);
    const int pc    = valid ? p : (M_PAIRS - 1);
    const int im    = in_map [k * M_PAIRS + pc];
    const int om    = valid ? out_map[k * M_PAIRS + pc] : -1;

    if (t == 0) { MBAR_INIT(sbase + SM_MBAR0, 1); MBAR_INIT(sbase + SM_MBAR1, 1); }
    __syncthreads();
    if (t == 0) MBAR_EXPECT_TX(sbase + SM_MBAR0, 96 * 256 + B_BYTES);
    if (t == 1) MBAR_EXPECT_TX(sbase + SM_MBAR1, 96 * 256);

    // ---- gather A: one 256B bulk per row; B: ONE 17408B bulk (t==0) ----
    const uint32_t mybar = sbase + (t < 96 ? SM_MBAR0 : SM_MBAR1);
    BULK_CP(abase + t * ROWB, g_Xh + (size_t)im * C_IN, 256, mybar);
    if (t == 0)
        BULK_CP(bbase, g_Wsw + (size_t)k * (C_OUT * 136), B_BYTES,
                sbase + SM_MBAR0);

    MBAR_WAIT(sbase + SM_MBAR0, 0);
    if (w >= 3) MBAR_WAIT(sbase + SM_MBAR1, 0);

    // ---- MMA mainloop: warp w owns rows [32w, 32w+32), cols 0..63 ----
    float d[2][8][4];
    #pragma unroll
    for (int mt = 0; mt < 2; ++mt)
        #pragma unroll
        for (int nt = 0; nt < 8; ++nt)
            #pragma unroll
            for (int j = 0; j < 4; ++j) d[mt][nt][j] = 0.f;

    #pragma unroll
    for (int kc = 0; kc < 8; ++kc) {
        uint32_t a_frag[2][4];
        #pragma unroll
        for (int mt = 0; mt < 2; ++mt) {
            int row = w * 32 + mt * 16 + (lane & 15);
            int ch  = kc * 2 + (lane >> 4);
            LDMATRIX_X4(a_frag[mt], abase + row * ROWB + ch * 16);
        }
        uint32_t b_frag[4][4];
        #pragma unroll
        for (int nt2 = 0; nt2 < 4; ++nt2) {
            int n  = nt2 * 16 + ((lane >> 4) << 3) + (lane & 7);
            int ch = kc * 2 + ((lane >> 3) & 1);
            LDMATRIX_X4(b_frag[nt2], bbase + n * ROWB + ch * 16);
        }
        #pragma unroll
        for (int mt = 0; mt < 2; ++mt)
            #pragma unroll
            for (int nt = 0; nt < 8; ++nt)
                MMA16816(d[mt][nt], a_frag[mt],
                         b_frag[nt >> 1][(nt & 1) * 2],
                         b_frag[nt >> 1][(nt & 1) * 2 + 1]);
    }

    // ---- scatter-add straight from fragments; out rows fetched via shfl ----
    #pragma unroll
    for (int mt = 0; mt < 2; ++mt) {
        const int src  = mt * 16 + (lane >> 2);
        const int om0  = __shfl_sync(0xffffffffu, om, src);
        const int om1  = __shfl_sync(0xffffffffu, om, src + 8);
        float* dst0 = out + (size_t)om0 * C_OUT + (lane & 3) * 2;
        float* dst1 = out + (size_t)om1 * C_OUT + (lane & 3) * 2;
        #pragma unroll
        for (int nt = 0; nt < 8; ++nt) {
            if (om0 >= 0)
                asm volatile("red.global.add.v2.f32 [%0], {%1,%2};"
                             :: "l"(dst0 + nt * 8), "f"(d[mt][nt][0]), "f"(d[mt][nt][1])
                             : "memory");
            if (om1 >= 0)
                asm volatile("red.global.add.v2.f32 [%0], {%1,%2};"
                             :: "l"(dst1 + nt * 8), "f"(d[mt][nt][2]), "f"(d[mt][nt][3])
                             : "memory");
        }
    }
}

// ---------------- BN stats: float4 loads, one sync (R10-proven) -------------
__global__ void __launch_bounds__(256)
stats_kernel(const float* __restrict__ out)
{
    __shared__ float ss[16 * C_OUT], sq[16 * C_OUT];   // 2 x 4 KB
    const int t   = threadIdx.x;
    const int c4  = (t & 15) * 4;
    const int rep = t >> 4;
    float4 s = make_float4(0.f, 0.f, 0.f, 0.f);
    float4 q = make_float4(0.f, 0.f, 0.f, 0.f);
    for (int row = blockIdx.x * 16 + rep; row < N_OUTP; row += gridDim.x * 16) {
        const float4 v = *(const float4*)(out + (size_t)row * C_OUT + c4);
        s.x += v.x; q.x = fmaf(v.x, v.x, q.x);
        s.y += v.y; q.y = fmaf(v.y, v.y, q.y);
        s.z += v.z; q.z = fmaf(v.z, v.z, q.z);
        s.w += v.w; q.w = fmaf(v.w, v.w, q.w);
    }
    *(float4*)&ss[rep * C_OUT + c4] = s;
    *(float4*)&sq[rep * C_OUT + c4] = q;
    __syncthreads();
    if (t < C_OUT) {
        float as = 0.f, aq = 0.f;
        #pragma unroll
        for (int r = 0; r < 16; ++r) {
            as += ss[r * C_OUT + t];
            aq += sq[r * C_OUT + t];
        }
        atomicAdd(&g_sum[t],   as);
        atomicAdd(&g_sumsq[t], aq);
    }
}

// ---------------- normalize + ReLU (finalize folded in) ---------------------
__global__ void __launch_bounds__(256)
normalize_kernel(float* __restrict__ out,
                 const float* __restrict__ gamma,
                 const float* __restrict__ beta)
{
    __shared__ float sc[C_OUT], bs[C_OUT];
    if (threadIdx.x < C_OUT) {
        const int c = threadIdx.x;
        const float inv_n = 1.0f / (float)N_OUTP;
        const float mean = g_sum[c] * inv_n;
        const float var  = g_sumsq[c] * inv_n - mean * mean;
        const float s    = gamma[c] * rsqrtf(var + BN_EPS);
        sc[c] = s;
        bs[c] = beta[c] - mean * s;
    }
    __syncthreads();
    const int total4 = N_OUTP * C_OUT / 4;
    for (int i = blockIdx.x * blockDim.x + threadIdx.x; i < total4;
         i += gridDim.x * blockDim.x) {
        float4 v = ((float4*)out)[i];
        const int c0 = (i * 4) & 63;
        v.x = fmaxf(fmaf(v.x, sc[c0 + 0], bs[c0 + 0]), 0.f);
        v.y = fmaxf(fmaf(v.y, sc[c0 + 1], bs[c0 + 1]), 0.f);
        v.z = fmaxf(fmaf(v.z, sc[c0 + 2], bs[c0 + 2]), 0.f);
        v.w = fmaxf(fmaf(v.w, sc[c0 + 3], bs[c0 + 3]), 0.f);
        ((float4*)out)[i] = v;
    }
}

// ---------------- launch ----------------------------------------------------
extern "C" void kernel_launch(void* const* d_in, const int* in_sizes, int n_in,
                              void* d_out, int out_size)
{
    const float* x       = (const float*)d_in[0];
    const float* weight  = (const float*)d_in[1];
    const float* gamma   = (const float*)d_in[2];
    const float* beta    = (const float*)d_in[3];
    const int*   in_map  = (const int*)d_in[4];
    const int*   out_map = (const int*)d_in[5];
    float*       out     = (float*)d_out;

    cudaFuncSetAttribute(fused_kernel, cudaFuncAttributeMaxDynamicSharedMemorySize,
                         SMEM_FUSED);

    const int wblks = (KOFF * C_IN * C_OUT + 255) / 256;       // 864
    prep_kernel<<<XBLKS + wblks, 256>>>(x, weight, out, out_size / 4);

    {
        dim3 grid((M_PAIRS + PAIRS_BLK - 1) / PAIRS_BLK, KOFF);
        fused_kernel<<<grid, PAIRS_BLK, SMEM_FUSED>>>(in_map, out_map, out);
    }

    stats_kernel<<<1184, 256>>>(out);
    normalize_kernel<<<2048, 256>>>(out, gamma, beta);
}